// round 1
// baseline (speedup 1.0000x reference)
#include <cuda_runtime.h>
#include <cuda_bf16.h>

#define KC 16
#define DD 16
#define NQUAD 136          // i<=j pairs
#define NFEAT 152          // 136 quad + 16 linear

// Scratch (no cudaMalloc allowed): per-cluster feature coefficients + constants.
// g_coef layout: [feature][cluster]  (feature-major so the k-loop is contiguous)
__device__ float g_coef[NFEAT * KC];
__device__ float g_const[KC];

// ---------------------------------------------------------------------------
// f32x2 packed helpers (sm_103a packed FP32 pipe; ptxas never auto-emits these)
// ---------------------------------------------------------------------------
__device__ __forceinline__ unsigned long long f2pack(float lo, float hi) {
    unsigned long long r;
    asm("mov.b64 %0, {%1, %2};" : "=l"(r) : "f"(lo), "f"(hi));
    return r;
}
__device__ __forceinline__ unsigned long long f2mul(unsigned long long a, unsigned long long b) {
    unsigned long long r;
    asm("mul.rn.f32x2 %0, %1, %2;" : "=l"(r) : "l"(a), "l"(b));
    return r;
}
__device__ __forceinline__ unsigned long long f2fma(unsigned long long a, unsigned long long b,
                                                    unsigned long long c) {
    unsigned long long r;
    asm("fma.rn.f32x2 %0, %1, %2, %3;" : "=l"(r) : "l"(a), "l"(b), "l"(c));
    return r;
}

// ---------------------------------------------------------------------------
// Precompute kernel: one warp per cluster. Gauss-Jordan inverse of Sigma
// (column-owned: lane j holds column j), logdet from pivots, b = P*mu,
// then write feature coefficients:
//   quad (i<=j): -P_ij (i<j), -0.5*P_ii (i==j)
//   linear i:    b_i
//   const:       log pi_k - 0.5*logdet - 0.5*D*log(2pi) - 0.5*mu^T P mu
// ---------------------------------------------------------------------------
__global__ void gmm_precompute(const float* __restrict__ pi,
                               const float* __restrict__ mu,
                               const float* __restrict__ Sigma) {
    const int w    = threadIdx.x >> 5;   // cluster index (16 warps)
    const int lane = threadIdx.x & 31;
    const int j    = lane & 15;          // lanes 16..31 mirror 0..15 (harmless dup)

    float a[16], inv[16];
#pragma unroll
    for (int i = 0; i < 16; ++i) {
        a[i]   = Sigma[w * 256 + i * 16 + j];
        inv[i] = (i == j) ? 1.0f : 0.0f;
    }

    float logdet = 0.0f;
#pragma unroll
    for (int k = 0; k < 16; ++k) {
        float piv = __shfl_sync(0xffffffffu, a[k], k);
        logdet += logf(piv);
        float ip = 1.0f / piv;
        a[k]   *= ip;
        inv[k] *= ip;
#pragma unroll
        for (int i = 0; i < 16; ++i) {
            if (i != k) {
                float m = __shfl_sync(0xffffffffu, a[i], k);  // A[i][k] before row-i update
                a[i]   = fmaf(-m, a[k],   a[i]);
                inv[i] = fmaf(-m, inv[k], inv[i]);
            }
        }
    }

    // b = P mu   (lane j contributes inv[i]*mu_j; butterfly-sum over 16-lane group)
    const float mu_j = mu[w * 16 + j];
    float bv[16];
#pragma unroll
    for (int i = 0; i < 16; ++i) {
        float v = inv[i] * mu_j;
        v += __shfl_xor_sync(0xffffffffu, v, 8);
        v += __shfl_xor_sync(0xffffffffu, v, 4);
        v += __shfl_xor_sync(0xffffffffu, v, 2);
        v += __shfl_xor_sync(0xffffffffu, v, 1);
        bv[i] = v;
    }
    float muPmu = 0.0f;
#pragma unroll
    for (int i = 0; i < 16; ++i) muPmu += bv[i] * mu[w * 16 + i];

    if (lane < 16) {
#pragma unroll
        for (int i = 0; i < 16; ++i) {
            if (i <= j) {
                float c = (i == j ? -0.5f : -1.0f) * inv[i];   // inv[i] = P[i][j]
                g_coef[(j * (j + 1) / 2 + i) * KC + w] = c;
            }
        }
    }
    if (lane == 0) {
#pragma unroll
        for (int i = 0; i < 16; ++i) g_coef[(NQUAD + i) * KC + w] = bv[i];
        // 0.5*D*log(2pi) = 8 * 1.83787706641...
        g_const[w] = logf(pi[w]) - 0.5f * logdet - 8.0f * 1.8378770664093453f - 0.5f * muPmu;
    }
}

// ---------------------------------------------------------------------------
// Main kernel: each thread computes TWO points packed in f32x2 lanes.
// smem holds coefficients duplicated (c,c) so fma.rn.f32x2 applies the same
// coefficient to both points. 152 features x 16 clusters, then per-point
// softmax and float4 stores.
// ---------------------------------------------------------------------------
__global__ void __launch_bounds__(256) gmm_main(const float* __restrict__ x,
                                                float* __restrict__ out, int n) {
    __shared__ ulonglong2 s_coef[NFEAT * 8];          // [feature][k2]  (k2 = pair of clusters)
    __shared__ unsigned long long s_const[KC];

    {
        unsigned long long* flat = reinterpret_cast<unsigned long long*>(s_coef);
        for (int idx = threadIdx.x; idx < NFEAT * KC; idx += blockDim.x) {
            float c = g_coef[idx];
            flat[idx] = f2pack(c, c);
        }
        if (threadIdx.x < KC) {
            float c = g_const[threadIdx.x];
            s_const[threadIdx.x] = f2pack(c, c);
        }
    }
    __syncthreads();

    long long t  = (long long)blockIdx.x * blockDim.x + threadIdx.x;
    long long n0 = 2 * t;
    if (n0 >= n) return;
    const bool hasB = (n0 + 1 < n);

    const float4* xA = reinterpret_cast<const float4*>(x + n0 * DD);
    const float4* xB = reinterpret_cast<const float4*>(x + (hasB ? (n0 + 1) : n0) * DD);

    unsigned long long X[16];
#pragma unroll
    for (int q = 0; q < 4; ++q) {
        float4 va = xA[q], vb = xB[q];
        X[4 * q + 0] = f2pack(va.x, vb.x);
        X[4 * q + 1] = f2pack(va.y, vb.y);
        X[4 * q + 2] = f2pack(va.z, vb.z);
        X[4 * q + 3] = f2pack(va.w, vb.w);
    }

    unsigned long long acc[16];
#pragma unroll
    for (int k = 0; k < 16; ++k) acc[k] = s_const[k];

    // quadratic features (i<=j), feature index p = j*(j+1)/2 + i
    int p = 0;
#pragma unroll
    for (int j = 0; j < 16; ++j) {
#pragma unroll
        for (int i = 0; i <= j; ++i) {
            unsigned long long f2 = f2mul(X[i], X[j]);
#pragma unroll
            for (int k2 = 0; k2 < 8; ++k2) {
                ulonglong2 cc = s_coef[p * 8 + k2];
                acc[2 * k2]     = f2fma(cc.x, f2, acc[2 * k2]);
                acc[2 * k2 + 1] = f2fma(cc.y, f2, acc[2 * k2 + 1]);
            }
            ++p;
        }
    }
    // linear features
#pragma unroll
    for (int i = 0; i < 16; ++i) {
        unsigned long long f2 = X[i];
#pragma unroll
        for (int k2 = 0; k2 < 8; ++k2) {
            ulonglong2 cc = s_coef[(NQUAD + i) * 8 + k2];
            acc[2 * k2]     = f2fma(cc.x, f2, acc[2 * k2]);
            acc[2 * k2 + 1] = f2fma(cc.y, f2, acc[2 * k2 + 1]);
        }
    }

    // unpack
    float la[16], lb[16];
#pragma unroll
    for (int k = 0; k < 16; ++k) {
        unsigned int lo, hi;
        asm("mov.b64 {%0, %1}, %2;" : "=r"(lo), "=r"(hi) : "l"(acc[k]));
        la[k] = __uint_as_float(lo);
        lb[k] = __uint_as_float(hi);
    }

    // softmax + store, point A
    {
        float m = la[0];
#pragma unroll
        for (int k = 1; k < 16; ++k) m = fmaxf(m, la[k]);
        float e[16], s = 0.0f;
#pragma unroll
        for (int k = 0; k < 16; ++k) { e[k] = __expf(la[k] - m); s += e[k]; }
        float r = __fdividef(1.0f, s);
        float4* o = reinterpret_cast<float4*>(out + n0 * KC);
        o[0] = make_float4(e[0] * r,  e[1] * r,  e[2] * r,  e[3] * r);
        o[1] = make_float4(e[4] * r,  e[5] * r,  e[6] * r,  e[7] * r);
        o[2] = make_float4(e[8] * r,  e[9] * r,  e[10] * r, e[11] * r);
        o[3] = make_float4(e[12] * r, e[13] * r, e[14] * r, e[15] * r);
    }
    // point B
    if (hasB) {
        float m = lb[0];
#pragma unroll
        for (int k = 1; k < 16; ++k) m = fmaxf(m, lb[k]);
        float e[16], s = 0.0f;
#pragma unroll
        for (int k = 0; k < 16; ++k) { e[k] = __expf(lb[k] - m); s += e[k]; }
        float r = __fdividef(1.0f, s);
        float4* o = reinterpret_cast<float4*>(out + (n0 + 1) * KC);
        o[0] = make_float4(e[0] * r,  e[1] * r,  e[2] * r,  e[3] * r);
        o[1] = make_float4(e[4] * r,  e[5] * r,  e[6] * r,  e[7] * r);
        o[2] = make_float4(e[8] * r,  e[9] * r,  e[10] * r, e[11] * r);
        o[3] = make_float4(e[12] * r, e[13] * r, e[14] * r, e[15] * r);
    }
}

extern "C" void kernel_launch(void* const* d_in, const int* in_sizes, int n_in,
                              void* d_out, int out_size) {
    const float* x     = (const float*)d_in[0];
    const float* pi    = (const float*)d_in[1];
    const float* mu    = (const float*)d_in[2];
    const float* Sigma = (const float*)d_in[3];
    float* out = (float*)d_out;

    int n = in_sizes[0] / DD;  // number of points

    gmm_precompute<<<1, 512>>>(pi, mu, Sigma);

    int nthreads = (n + 1) / 2;  // 2 points per thread
    int block = 256;
    int grid  = (nthreads + block - 1) / block;
    gmm_main<<<grid, block>>>(x, out, n);
}

// round 2
// speedup vs baseline: 1.3463x; 1.3463x over previous
#include <cuda_runtime.h>
#include <cuda_bf16.h>

#define KC 16
#define DD 16
#define NQUAD 136          // i<=j pairs
#define NFEAT 152          // 136 quad + 16 linear

// Scratch: per-cluster feature coefficients + constants.
// g_coef layout: [feature][cluster]  (cluster contiguous -> float4 LDS in main)
__device__ float g_coef[NFEAT * KC];
__device__ float g_const[KC];

// ---------------------------------------------------------------------------
// f32x2 packed helpers
// ---------------------------------------------------------------------------
__device__ __forceinline__ unsigned long long f2dup(float v) {
    unsigned long long r;
    asm("mov.b64 %0, {%1, %1};" : "=l"(r) : "f"(v));
    return r;
}
__device__ __forceinline__ unsigned long long f2mul(unsigned long long a, unsigned long long b) {
    unsigned long long r;
    asm("mul.rn.f32x2 %0, %1, %2;" : "=l"(r) : "l"(a), "l"(b));
    return r;
}
__device__ __forceinline__ unsigned long long f2fma(unsigned long long a, unsigned long long b,
                                                    unsigned long long c) {
    unsigned long long r;
    asm("fma.rn.f32x2 %0, %1, %2, %3;" : "=l"(r) : "l"(a), "l"(b), "l"(c));
    return r;
}
__device__ __forceinline__ void f2unpack(unsigned long long v, float& lo, float& hi) {
    asm("mov.b64 {%0, %1}, %2;" : "=f"(lo), "=f"(hi) : "l"(v));
}

// ---------------------------------------------------------------------------
// Precompute kernel: one warp per cluster. Gauss-Jordan inverse of Sigma
// (column-owned: lane j holds column j), logdet from pivots, b = P*mu.
// ---------------------------------------------------------------------------
__global__ void gmm_precompute(const float* __restrict__ pi,
                               const float* __restrict__ mu,
                               const float* __restrict__ Sigma) {
    const int w    = threadIdx.x >> 5;   // cluster index (16 warps)
    const int lane = threadIdx.x & 31;
    const int j    = lane & 15;          // lanes 16..31 mirror 0..15 (harmless dup)

    float a[16], inv[16];
#pragma unroll
    for (int i = 0; i < 16; ++i) {
        a[i]   = Sigma[w * 256 + i * 16 + j];
        inv[i] = (i == j) ? 1.0f : 0.0f;
    }

    float logdet = 0.0f;
#pragma unroll
    for (int k = 0; k < 16; ++k) {
        float piv = __shfl_sync(0xffffffffu, a[k], k);
        logdet += logf(piv);
        float ip = 1.0f / piv;
        a[k]   *= ip;
        inv[k] *= ip;
#pragma unroll
        for (int i = 0; i < 16; ++i) {
            if (i != k) {
                float m = __shfl_sync(0xffffffffu, a[i], k);
                a[i]   = fmaf(-m, a[k],   a[i]);
                inv[i] = fmaf(-m, inv[k], inv[i]);
            }
        }
    }

    // b = P mu   (lane j contributes inv[i]*mu_j; butterfly-sum over 16-lane group)
    const float mu_j = mu[w * 16 + j];
    float bv[16];
#pragma unroll
    for (int i = 0; i < 16; ++i) {
        float v = inv[i] * mu_j;
        v += __shfl_xor_sync(0xffffffffu, v, 8);
        v += __shfl_xor_sync(0xffffffffu, v, 4);
        v += __shfl_xor_sync(0xffffffffu, v, 2);
        v += __shfl_xor_sync(0xffffffffu, v, 1);
        bv[i] = v;
    }
    float muPmu = 0.0f;
#pragma unroll
    for (int i = 0; i < 16; ++i) muPmu += bv[i] * mu[w * 16 + i];

    if (lane < 16) {
#pragma unroll
        for (int i = 0; i < 16; ++i) {
            if (i <= j) {
                float c = (i == j ? -0.5f : -1.0f) * inv[i];   // inv[i] = P[i][j]
                g_coef[(j * (j + 1) / 2 + i) * KC + w] = c;
            }
        }
    }
    if (lane == 0) {
#pragma unroll
        for (int i = 0; i < 16; ++i) g_coef[(NQUAD + i) * KC + w] = bv[i];
        g_const[w] = logf(pi[w]) - 0.5f * logdet - 8.0f * 1.8378770664093453f - 0.5f * muPmu;
    }
}

// ---------------------------------------------------------------------------
// Main kernel: cluster-packed f32x2. Each thread computes 2 points; X values
// are pre-duplicated (x,x) so products come out duplicated, and accumulators
// pack 2 adjacent clusters per f32x2. Coefficients live in smem as plain
// floats [feature][16]: one LDS.128 feeds 4 clusters -> 4 LDS per feature
// shared across both points (vs 8 in the point-packed scheme).
// ---------------------------------------------------------------------------
__global__ void __launch_bounds__(256) gmm_main(const float* __restrict__ x,
                                                float* __restrict__ out, int n) {
    __shared__ __align__(16) float s_coef[NFEAT * KC];   // [feature][cluster]
    __shared__ __align__(16) float s_const[KC];

    for (int idx = threadIdx.x; idx < NFEAT * KC; idx += blockDim.x)
        s_coef[idx] = g_coef[idx];
    if (threadIdx.x < KC) s_const[threadIdx.x] = g_const[threadIdx.x];
    __syncthreads();

    long long t  = (long long)blockIdx.x * blockDim.x + threadIdx.x;
    long long n0 = 2 * t;
    if (n0 >= n) return;
    const bool hasB = (n0 + 1 < n);

    const float4* xA = reinterpret_cast<const float4*>(x + n0 * DD);
    const float4* xB = reinterpret_cast<const float4*>(x + (hasB ? (n0 + 1) : n0) * DD);

    unsigned long long XA[16], XB[16];
#pragma unroll
    for (int q = 0; q < 4; ++q) {
        float4 va = xA[q], vb = xB[q];
        XA[4 * q + 0] = f2dup(va.x); XA[4 * q + 1] = f2dup(va.y);
        XA[4 * q + 2] = f2dup(va.z); XA[4 * q + 3] = f2dup(va.w);
        XB[4 * q + 0] = f2dup(vb.x); XB[4 * q + 1] = f2dup(vb.y);
        XB[4 * q + 2] = f2dup(vb.z); XB[4 * q + 3] = f2dup(vb.w);
    }

    // acc[m] holds clusters (2m, 2m+1) packed; separate for the two points.
    unsigned long long accA[8], accB[8];
    {
        const unsigned long long* cu = reinterpret_cast<const unsigned long long*>(s_const);
#pragma unroll
        for (int m = 0; m < 8; ++m) { accA[m] = cu[m]; accB[m] = cu[m]; }
    }

    // quadratic features (i<=j), feature p = j*(j+1)/2 + i
    int p = 0;
#pragma unroll
    for (int j = 0; j < 16; ++j) {
#pragma unroll
        for (int i = 0; i <= j; ++i) {
            unsigned long long fA = f2mul(XA[i], XA[j]);
            unsigned long long fB = f2mul(XB[i], XB[j]);
            const ulonglong2* cp = reinterpret_cast<const ulonglong2*>(s_coef + p * KC);
#pragma unroll
            for (int m = 0; m < 4; ++m) {
                ulonglong2 cc = cp[m];             // clusters 4m..4m+3
                accA[2 * m]     = f2fma(cc.x, fA, accA[2 * m]);
                accA[2 * m + 1] = f2fma(cc.y, fA, accA[2 * m + 1]);
                accB[2 * m]     = f2fma(cc.x, fB, accB[2 * m]);
                accB[2 * m + 1] = f2fma(cc.y, fB, accB[2 * m + 1]);
            }
            ++p;
        }
    }
    // linear features (X already duplicated)
#pragma unroll
    for (int i = 0; i < 16; ++i) {
        const ulonglong2* cp = reinterpret_cast<const ulonglong2*>(s_coef + (NQUAD + i) * KC);
#pragma unroll
        for (int m = 0; m < 4; ++m) {
            ulonglong2 cc = cp[m];
            accA[2 * m]     = f2fma(cc.x, XA[i], accA[2 * m]);
            accA[2 * m + 1] = f2fma(cc.y, XA[i], accA[2 * m + 1]);
            accB[2 * m]     = f2fma(cc.x, XB[i], accB[2 * m]);
            accB[2 * m + 1] = f2fma(cc.y, XB[i], accB[2 * m + 1]);
        }
    }

    // unpack logits
    float la[16], lb[16];
#pragma unroll
    for (int m = 0; m < 8; ++m) {
        f2unpack(accA[m], la[2 * m], la[2 * m + 1]);
        f2unpack(accB[m], lb[2 * m], lb[2 * m + 1]);
    }

    // softmax + store, point A
    {
        float mx = la[0];
#pragma unroll
        for (int k = 1; k < 16; ++k) mx = fmaxf(mx, la[k]);
        float e[16], s = 0.0f;
#pragma unroll
        for (int k = 0; k < 16; ++k) { e[k] = __expf(la[k] - mx); s += e[k]; }
        float r = __fdividef(1.0f, s);
        float4* o = reinterpret_cast<float4*>(out + n0 * KC);
        o[0] = make_float4(e[0] * r,  e[1] * r,  e[2] * r,  e[3] * r);
        o[1] = make_float4(e[4] * r,  e[5] * r,  e[6] * r,  e[7] * r);
        o[2] = make_float4(e[8] * r,  e[9] * r,  e[10] * r, e[11] * r);
        o[3] = make_float4(e[12] * r, e[13] * r, e[14] * r, e[15] * r);
    }
    // point B
    if (hasB) {
        float mx = lb[0];
#pragma unroll
        for (int k = 1; k < 16; ++k) mx = fmaxf(mx, lb[k]);
        float e[16], s = 0.0f;
#pragma unroll
        for (int k = 0; k < 16; ++k) { e[k] = __expf(lb[k] - mx); s += e[k]; }
        float r = __fdividef(1.0f, s);
        float4* o = reinterpret_cast<float4*>(out + (n0 + 1) * KC);
        o[0] = make_float4(e[0] * r,  e[1] * r,  e[2] * r,  e[3] * r);
        o[1] = make_float4(e[4] * r,  e[5] * r,  e[6] * r,  e[7] * r);
        o[2] = make_float4(e[8] * r,  e[9] * r,  e[10] * r, e[11] * r);
        o[3] = make_float4(e[12] * r, e[13] * r, e[14] * r, e[15] * r);
    }
}

extern "C" void kernel_launch(void* const* d_in, const int* in_sizes, int n_in,
                              void* d_out, int out_size) {
    const float* x     = (const float*)d_in[0];
    const float* pi    = (const float*)d_in[1];
    const float* mu    = (const float*)d_in[2];
    const float* Sigma = (const float*)d_in[3];
    float* out = (float*)d_out;

    int n = in_sizes[0] / DD;  // number of points

    gmm_precompute<<<1, 512>>>(pi, mu, Sigma);

    int nthreads = (n + 1) / 2;  // 2 points per thread
    int block = 256;
    int grid  = (nthreads + block - 1) / block;
    gmm_main<<<grid, block>>>(x, out, n);
}